// round 1
// baseline (speedup 1.0000x reference)
#include <cuda_runtime.h>

#define NPTS   4096
#define BATCH  4
#define TPB    256
#define ITILE  4
#define IPB    (ITILE * TPB)          // 1024 i-points per block
#define NIBLK  (NPTS / IPB)           // 4
#define JSPLIT 8
#define JCHUNK (NPTS / JSPLIT)        // 512
#define JTILE  TPB                    // 256 j-points per smem tile
#define NZ     (3 * BATCH)            // 12 (term, batch) pairs
#define NBLOCKS (NIBLK * JSPLIT * NZ) // 384

__device__ float g_partials[NBLOCKS];

// sqrt(log2(e)) — prescale coords so exp(-S) == exp2f(-S_scaled)
#define COORD_SCALE 1.2011224087864498f

__global__ void __launch_bounds__(TPB)
varifold_partial(const float* __restrict__ xyz1,
                 const float* __restrict__ xyz2,
                 const float* __restrict__ nor1,
                 const float* __restrict__ nor2)
{
    __shared__ float sx[JTILE * 3];
    __shared__ float sn[JTILE * 3];
    __shared__ float warpsum[TPB / 32];

    const int tid  = threadIdx.x;
    const int iblk = blockIdx.x;          // 0..NIBLK-1
    const int jblk = blockIdx.y;          // 0..JSPLIT-1
    const int zb   = blockIdx.z;          // 0..NZ-1
    const int term = zb / BATCH;          // 0: xx, 1: yy, 2: xy
    const int b    = zb % BATCH;

    const float* xa; const float* xb; const float* na; const float* nb;
    float w;
    if (term == 0)      { xa = xyz1; xb = xyz1; na = nor1; nb = nor1; w =  1.0f; }
    else if (term == 1) { xa = xyz2; xb = xyz2; na = nor2; nb = nor2; w =  1.0f; }
    else                { xa = xyz1; xb = xyz2; na = nor1; nb = nor2; w = -2.0f; }

    const long boff = (long)b * NPTS * 3;
    xa += boff; xb += boff; na += boff; nb += boff;

    // Register-resident i points (pre-scaled coords)
    float xi[ITILE][3], ni[ITILE][3], acc[ITILE];
    #pragma unroll
    for (int t = 0; t < ITILE; t++) {
        const int i = iblk * IPB + t * TPB + tid;
        xi[t][0] = xa[i * 3 + 0] * COORD_SCALE;
        xi[t][1] = xa[i * 3 + 1] * COORD_SCALE;
        xi[t][2] = xa[i * 3 + 2] * COORD_SCALE;
        ni[t][0] = na[i * 3 + 0];
        ni[t][1] = na[i * 3 + 1];
        ni[t][2] = na[i * 3 + 2];
        acc[t]   = 0.0f;
    }

    const int jbeg = jblk * JCHUNK;
    for (int j0 = jbeg; j0 < jbeg + JCHUNK; j0 += JTILE) {
        __syncthreads();
        {
            const int j = j0 + tid;
            sx[tid * 3 + 0] = xb[j * 3 + 0] * COORD_SCALE;
            sx[tid * 3 + 1] = xb[j * 3 + 1] * COORD_SCALE;
            sx[tid * 3 + 2] = xb[j * 3 + 2] * COORD_SCALE;
            sn[tid * 3 + 0] = nb[j * 3 + 0];
            sn[tid * 3 + 1] = nb[j * 3 + 1];
            sn[tid * 3 + 2] = nb[j * 3 + 2];
        }
        __syncthreads();

        #pragma unroll 4
        for (int jj = 0; jj < JTILE; jj++) {
            const float bx = sx[jj * 3 + 0];
            const float by = sx[jj * 3 + 1];
            const float bz = sx[jj * 3 + 2];
            const float mx = sn[jj * 3 + 0];
            const float my = sn[jj * 3 + 1];
            const float mz = sn[jj * 3 + 2];
            #pragma unroll
            for (int t = 0; t < ITILE; t++) {
                const float dx = xi[t][0] - bx;
                const float dy = xi[t][1] - by;
                const float dz = xi[t][2] - bz;
                float S = dx * dx;
                S = fmaf(dy, dy, S);
                S = fmaf(dz, dz, S);
                float D = ni[t][0] * mx;
                D = fmaf(ni[t][1], my, D);
                D = fmaf(ni[t][2], mz, D);
                const float e  = exp2f(-S);    // MUFU.EX2 with free negate
                const float d2 = D * D;
                acc[t] = fmaf(e, d2, acc[t]);
            }
        }
    }

    // Block reduction (deterministic)
    float v = (acc[0] + acc[1]) + (acc[2] + acc[3]);
    #pragma unroll
    for (int o = 16; o > 0; o >>= 1)
        v += __shfl_xor_sync(0xffffffffu, v, o);
    if ((tid & 31) == 0) warpsum[tid >> 5] = v;
    __syncthreads();
    if (tid == 0) {
        float s = 0.0f;
        #pragma unroll
        for (int k = 0; k < TPB / 32; k++) s += warpsum[k];
        const int blin = (blockIdx.z * gridDim.y + blockIdx.y) * gridDim.x + blockIdx.x;
        g_partials[blin] = s * w;
    }
}

__global__ void __launch_bounds__(TPB)
varifold_finalize(float* __restrict__ out)
{
    __shared__ float warpsum[TPB / 32];
    const int tid = threadIdx.x;
    float v = 0.0f;
    for (int i = tid; i < NBLOCKS; i += TPB)
        v += g_partials[i];
    #pragma unroll
    for (int o = 16; o > 0; o >>= 1)
        v += __shfl_xor_sync(0xffffffffu, v, o);
    if ((tid & 31) == 0) warpsum[tid >> 5] = v;
    __syncthreads();
    if (tid == 0) {
        float s = 0.0f;
        #pragma unroll
        for (int k = 0; k < TPB / 32; k++) s += warpsum[k];
        out[0] = s;
    }
}

extern "C" void kernel_launch(void* const* d_in, const int* in_sizes, int n_in,
                              void* d_out, int out_size)
{
    const float* xyz1 = (const float*)d_in[0];
    const float* xyz2 = (const float*)d_in[1];
    const float* nor1 = (const float*)d_in[2];
    const float* nor2 = (const float*)d_in[3];

    dim3 grid(NIBLK, JSPLIT, NZ);
    varifold_partial<<<grid, TPB>>>(xyz1, xyz2, nor1, nor2);
    varifold_finalize<<<1, TPB>>>((float*)d_out);
}

// round 2
// speedup vs baseline: 1.5953x; 1.5953x over previous
#include <cuda_runtime.h>

#define NPTS   4096
#define BATCH  4
#define TPB    256
#define ITILE  4
#define IPB    (ITILE * TPB)          // 1024 i-points per block
#define NIBLK  (NPTS / IPB)           // 4
#define JSPLIT 16
#define JCHUNK (NPTS / JSPLIT)        // 256
#define JTILE  JCHUNK                 // one smem tile per block
#define NZ     (3 * BATCH)            // 12 (term, batch) pairs
#define NBLOCKS (NIBLK * JSPLIT * NZ) // 768

// sqrt(log2(e)): p = x*SCALE  =>  p_i.p_j = log2(e) * x_i.x_j
#define COORD_SCALE 1.2011224087864498f

__device__ float g_partials[NBLOCKS];
__device__ unsigned int g_count = 0;

typedef unsigned long long ull;

__device__ __forceinline__ ull pack2(float lo, float hi) {
    ull r;
    asm("mov.b64 %0, {%1, %2};" : "=l"(r) : "f"(lo), "f"(hi));
    return r;
}
__device__ __forceinline__ void unpack2(ull v, float& lo, float& hi) {
    asm("mov.b64 {%0, %1}, %2;" : "=f"(lo), "=f"(hi) : "l"(v));
}
__device__ __forceinline__ ull fma2(ull a, ull b, ull c) {
    ull d;
    asm("fma.rn.f32x2 %0, %1, %2, %3;" : "=l"(d) : "l"(a), "l"(b), "l"(c));
    return d;
}
__device__ __forceinline__ ull mul2(ull a, ull b) {
    ull d;
    asm("mul.rn.f32x2 %0, %1, %2;" : "=l"(d) : "l"(a), "l"(b));
    return d;
}
__device__ __forceinline__ ull add2(ull a, ull b) {
    ull d;
    asm("add.rn.f32x2 %0, %1, %2;" : "=l"(d) : "l"(a), "l"(b));
    return d;
}
__device__ __forceinline__ float ex2(float x) {
    float r;
    asm("ex2.approx.ftz.f32 %0, %1;" : "=f"(r) : "f"(x));
    return r;
}

__global__ void __launch_bounds__(TPB)
varifold_fused(const float* __restrict__ xyz1,
               const float* __restrict__ xyz2,
               const float* __restrict__ nor1,
               const float* __restrict__ nor2,
               float* __restrict__ out)
{
    // SoA j-tile: packed-friendly (adjacent j's contiguous), 8B-aligned
    __shared__ __align__(16) float sqx[JTILE], sqy[JTILE], sqz[JTILE], scj[JTILE];
    __shared__ __align__(16) float smx[JTILE], smy[JTILE], smz[JTILE];
    __shared__ float warpsum[TPB / 32];

    const int tid  = threadIdx.x;
    const int iblk = blockIdx.x;          // 0..NIBLK-1
    const int jblk = blockIdx.y;          // 0..JSPLIT-1
    const int zb   = blockIdx.z;          // 0..NZ-1
    const int term = zb / BATCH;          // 0: xx, 1: yy, 2: xy
    const int b    = zb % BATCH;

    const float* xa; const float* xb; const float* na; const float* nb;
    float w;
    if (term == 0)      { xa = xyz1; xb = xyz1; na = nor1; nb = nor1; w =  1.0f; }
    else if (term == 1) { xa = xyz2; xb = xyz2; na = nor2; nb = nor2; w =  1.0f; }
    else                { xa = xyz1; xb = xyz2; na = nor1; nb = nor2; w = -2.0f; }

    const long boff = (long)b * NPTS * 3;
    xa += boff; xb += boff; na += boff; nb += boff;

    // --- load + transform j tile into SMEM (one tile per block) ---
    {
        const int j = jblk * JCHUNK + tid;
        const float qx = xb[j * 3 + 0] * COORD_SCALE;
        const float qy = xb[j * 3 + 1] * COORD_SCALE;
        const float qz = xb[j * 3 + 2] * COORD_SCALE;
        sqx[tid] = qx;  sqy[tid] = qy;  sqz[tid] = qz;
        scj[tid] = -0.5f * (qx * qx + qy * qy + qz * qz);
        smx[tid] = nb[j * 3 + 0];
        smy[tid] = nb[j * 3 + 1];
        smz[tid] = nb[j * 3 + 2];
    }

    // --- register-resident i points, duplicated into both f32x2 lanes ---
    ull px[ITILE], py[ITILE], pz[ITILE], ci[ITILE];
    ull nx[ITILE], ny[ITILE], nz[ITILE], acc[ITILE];
    #pragma unroll
    for (int t = 0; t < ITILE; t++) {
        const int i = iblk * IPB + t * TPB + tid;
        const float ax = xa[i * 3 + 0] * COORD_SCALE;
        const float ay = xa[i * 3 + 1] * COORD_SCALE;
        const float az = xa[i * 3 + 2] * COORD_SCALE;
        const float c  = -0.5f * (ax * ax + ay * ay + az * az);
        px[t] = pack2(ax, ax);
        py[t] = pack2(ay, ay);
        pz[t] = pack2(az, az);
        ci[t] = pack2(c, c);
        const float bx = na[i * 3 + 0];
        const float by = na[i * 3 + 1];
        const float bz = na[i * 3 + 2];
        nx[t] = pack2(bx, bx);
        ny[t] = pack2(by, by);
        nz[t] = pack2(bz, bz);
        acc[t] = 0ull;
    }
    __syncthreads();

    // --- main loop: 2 j-points per iteration via f32x2 ---
    #pragma unroll 2
    for (int jj = 0; jj < JTILE; jj += 2) {
        const ull qx2 = *(const ull*)&sqx[jj];
        const ull qy2 = *(const ull*)&sqy[jj];
        const ull qz2 = *(const ull*)&sqz[jj];
        const ull cj2 = *(const ull*)&scj[jj];
        const ull mx2 = *(const ull*)&smx[jj];
        const ull my2 = *(const ull*)&smy[jj];
        const ull mz2 = *(const ull*)&smz[jj];
        #pragma unroll
        for (int t = 0; t < ITILE; t++) {
            // arg = p_i.p_j + c_i + c_j  ( = -||x_i - x_j||^2 / 2 * log2(e) )
            ull a = fma2(px[t], qx2, ci[t]);
            a = fma2(py[t], qy2, a);
            a = fma2(pz[t], qz2, a);
            a = add2(a, cj2);
            // D = n_i . n_j
            ull d = mul2(nx[t], mx2);
            d = fma2(ny[t], my2, d);
            d = fma2(nz[t], mz2, d);
            // e = exp(-S/2); acc += (e*D)^2 = exp(-S)*D^2
            float a0, a1;
            unpack2(a, a0, a1);
            const ull e = pack2(ex2(a0), ex2(a1));
            const ull td = mul2(e, d);
            acc[t] = fma2(td, td, acc[t]);
        }
    }

    // --- block reduction (deterministic) ---
    float v = 0.0f;
    #pragma unroll
    for (int t = 0; t < ITILE; t++) {
        float a0, a1;
        unpack2(acc[t], a0, a1);
        v += a0 + a1;
    }
    #pragma unroll
    for (int o = 16; o > 0; o >>= 1)
        v += __shfl_xor_sync(0xffffffffu, v, o);
    if ((tid & 31) == 0) warpsum[tid >> 5] = v;
    __syncthreads();

    __shared__ bool is_last;
    if (tid == 0) {
        float s = 0.0f;
        #pragma unroll
        for (int k = 0; k < TPB / 32; k++) s += warpsum[k];
        const int blin = (blockIdx.z * gridDim.y + blockIdx.y) * gridDim.x + blockIdx.x;
        g_partials[blin] = s * w;
        __threadfence();
        const unsigned int done = atomicAdd(&g_count, 1u);
        is_last = (done == (unsigned int)(NBLOCKS - 1));
    }
    __syncthreads();

    // --- last block finalizes (fixed summation order => deterministic) ---
    if (is_last) {
        float r = 0.0f;
        for (int i = tid; i < NBLOCKS; i += TPB)
            r += __ldcg(&g_partials[i]);
        #pragma unroll
        for (int o = 16; o > 0; o >>= 1)
            r += __shfl_xor_sync(0xffffffffu, r, o);
        if ((tid & 31) == 0) warpsum[tid >> 5] = r;
        __syncthreads();
        if (tid == 0) {
            float s = 0.0f;
            #pragma unroll
            for (int k = 0; k < TPB / 32; k++) s += warpsum[k];
            out[0] = s;
            g_count = 0;   // reset for next graph replay
        }
    }
}

extern "C" void kernel_launch(void* const* d_in, const int* in_sizes, int n_in,
                              void* d_out, int out_size)
{
    const float* xyz1 = (const float*)d_in[0];
    const float* xyz2 = (const float*)d_in[1];
    const float* nor1 = (const float*)d_in[2];
    const float* nor2 = (const float*)d_in[3];

    dim3 grid(NIBLK, JSPLIT, NZ);
    varifold_fused<<<grid, TPB>>>(xyz1, xyz2, nor1, nor2, (float*)d_out);
}

// round 3
// speedup vs baseline: 2.1834x; 1.3687x over previous
#include <cuda_runtime.h>

#define NPTS    4096
#define BATCH   4
#define TPB     256
#define ITILE   2
#define TILE    512                    // square tile side (i and j extent per block)
#define T       (NPTS / TILE)          // 8 tiles per side
#define JSUB    256                    // smem sub-tile width
#define NSYM    (T * (T + 1) / 2)      // 36 tile-pairs per symmetric term
#define NCROSS  (T * T)                // 64 tile-pairs for cross term
#define BPB     (2 * NSYM + NCROSS)    // 136 blocks per batch
#define NBLOCKS (BPB * BATCH)          // 544

// sqrt(log2(e)): p = x*SCALE  =>  p_i.p_j = log2(e) * x_i.x_j
#define COORD_SCALE 1.2011224087864498f

__device__ float g_partials[NBLOCKS];
__device__ unsigned int g_count = 0;

typedef unsigned long long ull;

__device__ __forceinline__ ull pack2(float lo, float hi) {
    ull r;
    asm("mov.b64 %0, {%1, %2};" : "=l"(r) : "f"(lo), "f"(hi));
    return r;
}
__device__ __forceinline__ void unpack2(ull v, float& lo, float& hi) {
    asm("mov.b64 {%0, %1}, %2;" : "=f"(lo), "=f"(hi) : "l"(v));
}
__device__ __forceinline__ ull fma2(ull a, ull b, ull c) {
    ull d;
    asm("fma.rn.f32x2 %0, %1, %2, %3;" : "=l"(d) : "l"(a), "l"(b), "l"(c));
    return d;
}
__device__ __forceinline__ ull mul2(ull a, ull b) {
    ull d;
    asm("mul.rn.f32x2 %0, %1, %2;" : "=l"(d) : "l"(a), "l"(b));
    return d;
}
__device__ __forceinline__ ull add2(ull a, ull b) {
    ull d;
    asm("add.rn.f32x2 %0, %1, %2;" : "=l"(d) : "l"(a), "l"(b));
    return d;
}
__device__ __forceinline__ float ex2(float x) {
    float r;
    asm("ex2.approx.ftz.f32 %0, %1;" : "=f"(r) : "f"(x));
    return r;
}

__global__ void __launch_bounds__(TPB)
varifold_fused(const float* __restrict__ xyz1,
               const float* __restrict__ xyz2,
               const float* __restrict__ nor1,
               const float* __restrict__ nor2,
               float* __restrict__ out)
{
    __shared__ __align__(16) float sqx[JSUB], sqy[JSUB], sqz[JSUB], scj[JSUB];
    __shared__ __align__(16) float smx[JSUB], smy[JSUB], smz[JSUB];
    __shared__ float warpsum[TPB / 32];

    const int tid = threadIdx.x;
    const int b   = blockIdx.y;

    // ---- decode block -> (term, ti, tj, weight) ----
    int idx = blockIdx.x;              // 0..BPB-1
    int term, ti, tj;
    float w;
    if (idx < 2 * NSYM) {
        term = (idx < NSYM) ? 0 : 1;
        int k = (idx < NSYM) ? idx : idx - NSYM;
        ti = 0;
        while (k >= T - ti) { k -= T - ti; ti++; }
        tj = ti + k;
        w = (ti == tj) ? 1.0f : 2.0f;  // symmetric term: off-diag counted twice
    } else {
        term = 2;
        const int q = idx - 2 * NSYM;
        ti = q >> 3;                   // T == 8
        tj = q & (T - 1);
        w = -2.0f;
    }

    const float* xa; const float* xb; const float* na; const float* nb;
    if (term == 0)      { xa = xyz1; xb = xyz1; na = nor1; nb = nor1; }
    else if (term == 1) { xa = xyz2; xb = xyz2; na = nor2; nb = nor2; }
    else                { xa = xyz1; xb = xyz2; na = nor1; nb = nor2; }

    const long boff = (long)b * NPTS * 3;
    xa += boff; xb += boff; na += boff; nb += boff;

    // ---- register-resident i points, duplicated into both f32x2 lanes ----
    ull px[ITILE], py[ITILE], pz[ITILE], ci[ITILE];
    ull nx[ITILE], ny[ITILE], nz[ITILE], acc[ITILE];
    #pragma unroll
    for (int t = 0; t < ITILE; t++) {
        const int i = ti * TILE + t * TPB + tid;
        const float ax = xa[i * 3 + 0] * COORD_SCALE;
        const float ay = xa[i * 3 + 1] * COORD_SCALE;
        const float az = xa[i * 3 + 2] * COORD_SCALE;
        const float c  = -0.5f * (ax * ax + ay * ay + az * az);
        px[t] = pack2(ax, ax);
        py[t] = pack2(ay, ay);
        pz[t] = pack2(az, az);
        ci[t] = pack2(c, c);
        const float bx = na[i * 3 + 0];
        const float by = na[i * 3 + 1];
        const float bz = na[i * 3 + 2];
        nx[t] = pack2(bx, bx);
        ny[t] = pack2(by, by);
        nz[t] = pack2(bz, bz);
        acc[t] = 0ull;
    }

    // ---- j loop: TILE j's in JSUB-wide smem sub-tiles ----
    for (int j0 = tj * TILE; j0 < tj * TILE + TILE; j0 += JSUB) {
        __syncthreads();
        {
            const int j = j0 + tid;
            const float qx = xb[j * 3 + 0] * COORD_SCALE;
            const float qy = xb[j * 3 + 1] * COORD_SCALE;
            const float qz = xb[j * 3 + 2] * COORD_SCALE;
            sqx[tid] = qx;  sqy[tid] = qy;  sqz[tid] = qz;
            scj[tid] = -0.5f * (qx * qx + qy * qy + qz * qz);
            smx[tid] = nb[j * 3 + 0];
            smy[tid] = nb[j * 3 + 1];
            smz[tid] = nb[j * 3 + 2];
        }
        __syncthreads();

        #pragma unroll 4
        for (int jj = 0; jj < JSUB; jj += 2) {
            const ull qx2 = *(const ull*)&sqx[jj];
            const ull qy2 = *(const ull*)&sqy[jj];
            const ull qz2 = *(const ull*)&sqz[jj];
            const ull cj2 = *(const ull*)&scj[jj];
            const ull mx2 = *(const ull*)&smx[jj];
            const ull my2 = *(const ull*)&smy[jj];
            const ull mz2 = *(const ull*)&smz[jj];
            #pragma unroll
            for (int t = 0; t < ITILE; t++) {
                // arg = p_i.p_j + c_i + c_j  ( = -||x_i - x_j||^2 * log2(e) / ... )
                ull a = fma2(px[t], qx2, ci[t]);
                a = fma2(py[t], qy2, a);
                a = fma2(pz[t], qz2, a);
                a = add2(a, cj2);
                // D = n_i . n_j
                ull d = mul2(nx[t], mx2);
                d = fma2(ny[t], my2, d);
                d = fma2(nz[t], mz2, d);
                // acc += (exp(-S/2)*D)^2 = exp(-S)*D^2
                float a0, a1;
                unpack2(a, a0, a1);
                const ull e = pack2(ex2(a0), ex2(a1));
                const ull td = mul2(e, d);
                acc[t] = fma2(td, td, acc[t]);
            }
        }
    }

    // ---- block reduction (deterministic) ----
    float v = 0.0f;
    #pragma unroll
    for (int t = 0; t < ITILE; t++) {
        float a0, a1;
        unpack2(acc[t], a0, a1);
        v += a0 + a1;
    }
    #pragma unroll
    for (int o = 16; o > 0; o >>= 1)
        v += __shfl_xor_sync(0xffffffffu, v, o);
    if ((tid & 31) == 0) warpsum[tid >> 5] = v;
    __syncthreads();

    __shared__ bool is_last;
    if (tid == 0) {
        float s = 0.0f;
        #pragma unroll
        for (int k = 0; k < TPB / 32; k++) s += warpsum[k];
        const int blin = blockIdx.y * gridDim.x + blockIdx.x;
        g_partials[blin] = s * w;
        __threadfence();
        const unsigned int done = atomicAdd(&g_count, 1u);
        is_last = (done == (unsigned int)(NBLOCKS - 1));
    }
    __syncthreads();

    // ---- last block finalizes (fixed summation order => deterministic) ----
    if (is_last) {
        float r = 0.0f;
        for (int i = tid; i < NBLOCKS; i += TPB)
            r += __ldcg(&g_partials[i]);
        #pragma unroll
        for (int o = 16; o > 0; o >>= 1)
            r += __shfl_xor_sync(0xffffffffu, r, o);
        if ((tid & 31) == 0) warpsum[tid >> 5] = r;
        __syncthreads();
        if (tid == 0) {
            float s = 0.0f;
            #pragma unroll
            for (int k = 0; k < TPB / 32; k++) s += warpsum[k];
            out[0] = s;
            g_count = 0;   // reset for next graph replay
        }
    }
}

extern "C" void kernel_launch(void* const* d_in, const int* in_sizes, int n_in,
                              void* d_out, int out_size)
{
    const float* xyz1 = (const float*)d_in[0];
    const float* xyz2 = (const float*)d_in[1];
    const float* nor1 = (const float*)d_in[2];
    const float* nor2 = (const float*)d_in[3];

    dim3 grid(BPB, BATCH);
    varifold_fused<<<grid, TPB>>>(xyz1, xyz2, nor1, nor2, (float*)d_out);
}

// round 4
// speedup vs baseline: 2.2898x; 1.0487x over previous
#include <cuda_runtime.h>

#define NPTS    4096
#define BATCH   4
#define TPB     256
#define ITILE   2
#define TILE    512                    // square tile side
#define T       (NPTS / TILE)          // 8
#define JSUB    256                    // smem sub-tile width
#define NSYM    (T * (T + 1) / 2)      // 36
#define NCROSS  (T * T)                // 64
#define BPB     (2 * NSYM + NCROSS)    // 136
#define NBLOCKS (BPB * BATCH)          // 544

// sqrt(log2(e)): p = x*SCALE  =>  p_i.p_j = log2(e) * x_i.x_j
#define COORD_SCALE 1.2011224087864498f

__device__ float g_partials[NBLOCKS];
__device__ unsigned int g_count = 0;

typedef unsigned long long ull;

__device__ __forceinline__ ull pack2(float lo, float hi) {
    ull r;
    asm("mov.b64 %0, {%1, %2};" : "=l"(r) : "f"(lo), "f"(hi));
    return r;
}
__device__ __forceinline__ void unpack2(ull v, float& lo, float& hi) {
    asm("mov.b64 {%0, %1}, %2;" : "=f"(lo), "=f"(hi) : "l"(v));
}
__device__ __forceinline__ ull fma2(ull a, ull b, ull c) {
    ull d;
    asm("fma.rn.f32x2 %0, %1, %2, %3;" : "=l"(d) : "l"(a), "l"(b), "l"(c));
    return d;
}
__device__ __forceinline__ ull mul2(ull a, ull b) {
    ull d;
    asm("mul.rn.f32x2 %0, %1, %2;" : "=l"(d) : "l"(a), "l"(b));
    return d;
}
__device__ __forceinline__ float ex2(float x) {
    float r;
    asm("ex2.approx.ftz.f32 %0, %1;" : "=f"(r) : "f"(x));
    return r;
}

// j-tile: per j-pair (2 adjacent j's), 3 float4s:
//   [0] = {qx_e, qx_o, qy_e, qy_o}
//   [1] = {qz_e, qz_o, mx_e, mx_o}
//   [2] = {my_e, my_o, mz_e, mz_o}
// m = n_j * 2^{c_j} (exponent constant folded into normals)

__global__ void __launch_bounds__(TPB, 4)
varifold_fused(const float* __restrict__ xyz1,
               const float* __restrict__ xyz2,
               const float* __restrict__ nor1,
               const float* __restrict__ nor2,
               float* __restrict__ out)
{
    __shared__ __align__(16) float4 sb[(JSUB / 2) * 3];
    __shared__ float warpsum[TPB / 32];

    const int tid = threadIdx.x;
    const int b   = blockIdx.y;

    // ---- decode block -> (term, ti, tj, weight) ----
    int idx = blockIdx.x;
    int term, ti, tj;
    float w;
    if (idx < 2 * NSYM) {
        term = (idx < NSYM) ? 0 : 1;
        int k = (idx < NSYM) ? idx : idx - NSYM;
        ti = 0;
        while (k >= T - ti) { k -= T - ti; ti++; }
        tj = ti + k;
        w = (ti == tj) ? 1.0f : 2.0f;
    } else {
        term = 2;
        const int q = idx - 2 * NSYM;
        ti = q >> 3;
        tj = q & (T - 1);
        w = -2.0f;
    }

    const float* xa; const float* xb; const float* na; const float* nb;
    if (term == 0)      { xa = xyz1; xb = xyz1; na = nor1; nb = nor1; }
    else if (term == 1) { xa = xyz2; xb = xyz2; na = nor2; nb = nor2; }
    else                { xa = xyz1; xb = xyz2; na = nor1; nb = nor2; }

    const long boff = (long)b * NPTS * 3;
    xa += boff; xb += boff; na += boff; nb += boff;

    // ---- register-resident i points: p_i and n'_i = n_i * 2^{c_i} ----
    ull px[ITILE], py[ITILE], pz[ITILE];
    ull nx[ITILE], ny[ITILE], nz[ITILE], acc[ITILE];
    #pragma unroll
    for (int t = 0; t < ITILE; t++) {
        const int i = ti * TILE + t * TPB + tid;
        const float ax = xa[i * 3 + 0] * COORD_SCALE;
        const float ay = xa[i * 3 + 1] * COORD_SCALE;
        const float az = xa[i * 3 + 2] * COORD_SCALE;
        const float si = ex2(-0.5f * (ax * ax + ay * ay + az * az));
        const float bx = na[i * 3 + 0] * si;
        const float by = na[i * 3 + 1] * si;
        const float bz = na[i * 3 + 2] * si;
        px[t] = pack2(ax, ax);
        py[t] = pack2(ay, ay);
        pz[t] = pack2(az, az);
        nx[t] = pack2(bx, bx);
        ny[t] = pack2(by, by);
        nz[t] = pack2(bz, bz);
        acc[t] = 0ull;
    }

    // ---- j loop over TILE in JSUB-wide smem sub-tiles ----
    for (int j0 = tj * TILE; j0 < tj * TILE + TILE; j0 += JSUB) {
        __syncthreads();
        {
            const int j  = j0 + tid;
            const float qx = xb[j * 3 + 0] * COORD_SCALE;
            const float qy = xb[j * 3 + 1] * COORD_SCALE;
            const float qz = xb[j * 3 + 2] * COORD_SCALE;
            const float sj = ex2(-0.5f * (qx * qx + qy * qy + qz * qz));
            const float mx = nb[j * 3 + 0] * sj;
            const float my = nb[j * 3 + 1] * sj;
            const float mz = nb[j * 3 + 2] * sj;
            const int jp = tid >> 1;
            const int l  = tid & 1;
            float* base = (float*)&sb[jp * 3];
            base[0 + l] = qx;  base[2 + l] = qy;
            base[4 + l] = qz;  base[6 + l] = mx;
            base[8 + l] = my;  base[10 + l] = mz;
        }
        __syncthreads();

        const ulonglong2* jb = (const ulonglong2*)sb;
        #pragma unroll 2
        for (int jp = 0; jp < JSUB / 2; jp++) {
            const ulonglong2 u0 = jb[jp * 3 + 0];   // qx2, qy2
            const ulonglong2 u1 = jb[jp * 3 + 1];   // qz2, mx2
            const ulonglong2 u2 = jb[jp * 3 + 2];   // my2, mz2
            #pragma unroll
            for (int t = 0; t < ITILE; t++) {
                // dot = p_i . p_j   (exponent; constants folded into normals)
                ull a = mul2(px[t], u0.x);
                a = fma2(py[t], u0.y, a);
                a = fma2(pz[t], u1.x, a);
                // D' = n'_i . n'_j
                ull d = mul2(nx[t], u1.y);
                d = fma2(ny[t], u2.x, d);
                d = fma2(nz[t], u2.y, d);
                // acc += (2^dot * D')^2 = exp(-S) * D^2
                float a0, a1;
                unpack2(a, a0, a1);
                const ull e  = pack2(ex2(a0), ex2(a1));
                const ull td = mul2(e, d);
                acc[t] = fma2(td, td, acc[t]);
            }
        }
    }

    // ---- block reduction (deterministic) ----
    float v = 0.0f;
    #pragma unroll
    for (int t = 0; t < ITILE; t++) {
        float a0, a1;
        unpack2(acc[t], a0, a1);
        v += a0 + a1;
    }
    #pragma unroll
    for (int o = 16; o > 0; o >>= 1)
        v += __shfl_xor_sync(0xffffffffu, v, o);
    if ((tid & 31) == 0) warpsum[tid >> 5] = v;
    __syncthreads();

    __shared__ bool is_last;
    if (tid == 0) {
        float s = 0.0f;
        #pragma unroll
        for (int k = 0; k < TPB / 32; k++) s += warpsum[k];
        const int blin = blockIdx.y * gridDim.x + blockIdx.x;
        g_partials[blin] = s * w;
        __threadfence();
        const unsigned int done = atomicAdd(&g_count, 1u);
        is_last = (done == (unsigned int)(NBLOCKS - 1));
    }
    __syncthreads();

    // ---- last block finalizes (fixed order => deterministic) ----
    if (is_last) {
        float r = 0.0f;
        for (int i = tid; i < NBLOCKS; i += TPB)
            r += __ldcg(&g_partials[i]);
        #pragma unroll
        for (int o = 16; o > 0; o >>= 1)
            r += __shfl_xor_sync(0xffffffffu, r, o);
        if ((tid & 31) == 0) warpsum[tid >> 5] = r;
        __syncthreads();
        if (tid == 0) {
            float s = 0.0f;
            #pragma unroll
            for (int k = 0; k < TPB / 32; k++) s += warpsum[k];
            out[0] = s;
            g_count = 0;   // reset for next graph replay
        }
    }
}

extern "C" void kernel_launch(void* const* d_in, const int* in_sizes, int n_in,
                              void* d_out, int out_size)
{
    const float* xyz1 = (const float*)d_in[0];
    const float* xyz2 = (const float*)d_in[1];
    const float* nor1 = (const float*)d_in[2];
    const float* nor2 = (const float*)d_in[3];

    dim3 grid(BPB, BATCH);
    varifold_fused<<<grid, TPB>>>(xyz1, xyz2, nor1, nor2, (float*)d_out);
}